// round 2
// baseline (speedup 1.0000x reference)
#include <cuda_runtime.h>
#include <cuda_bf16.h>
#include <math_constants.h>

#define NN 20000
#define EE 640000

#define SC_DOT 1.6329931618554521f    // sqrt(8/3)
#define SC_B   0.5773502691896258f    // sqrt(1/3)
#define SC_V   (-0.04811252243246881f) // -0.5*sqrt(1/108)

// ---- device scratch (no runtime allocation allowed) ----
__device__ __align__(16) float g_proj[(size_t)NN * 800]; // qs[0:256) ks[256:512) qv[512:608) kv[608:704) vv[704:800)
__device__ __align__(16) float g_qv[(size_t)NN * 96];
__device__ __align__(16) float g_kv[(size_t)NN * 96];
__device__ __align__(16) float g_logit[(size_t)EE * 4];
__device__ __align__(16) float g_pairz[(size_t)EE * 16];
__device__ int   g_cnt[NN];
__device__ int   g_off[NN];
__device__ int   g_cur[NN];
__device__ int   g_el[EE];
__device__ __align__(16) float g_fin[(size_t)NN * 160];  // [s(64) | norm(32) | pair(64)]
__device__ __align__(16) float g_Bproj[64 * 800];
__device__ __align__(16) float g_wcat[160 * 64];

__global__ void k_init(int n) {
    int i = blockIdx.x * blockDim.x + threadIdx.x;
    if (i < n) { g_cnt[i] = 0; g_cur[i] = 0; }
}

__global__ void k_count(const int* __restrict__ ei, int E) {
    int e = blockIdx.x * blockDim.x + threadIdx.x;
    if (e < E) atomicAdd(&g_cnt[ei[e]], 1);
}

// single-block exclusive scan (1024 threads)
__global__ void k_scan(int n) {
    __shared__ int wsum[32];
    int tid = threadIdx.x;
    int per = (n + 1023) / 1024;
    int base = tid * per;
    int s = 0;
    for (int k = 0; k < per; k++) { int idx = base + k; if (idx < n) s += g_cnt[idx]; }
    int lane = tid & 31, w = tid >> 5;
    int v = s;
    #pragma unroll
    for (int o = 1; o < 32; o <<= 1) { int t = __shfl_up_sync(~0u, v, o); if (lane >= o) v += t; }
    if (lane == 31) wsum[w] = v;
    __syncthreads();
    if (w == 0) {
        int orig = wsum[lane], x = orig;
        #pragma unroll
        for (int o = 1; o < 32; o <<= 1) { int t = __shfl_up_sync(~0u, x, o); if (lane >= o) x += t; }
        wsum[lane] = x - orig;
    }
    __syncthreads();
    int run = v - s + wsum[w];
    for (int k = 0; k < per; k++) {
        int idx = base + k;
        if (idx < n) { g_off[idx] = run; run += g_cnt[idx]; }
    }
}

__global__ void k_scatter(const int* __restrict__ ei, int E) {
    int e = blockIdx.x * blockDim.x + threadIdx.x;
    if (e < E) {
        int i = ei[e];
        int p = atomicAdd(&g_cur[i], 1);
        g_el[g_off[i] + p] = e;
    }
}

__global__ void k_pack(const float* __restrict__ Wq_s, const float* __restrict__ Wk_s,
                       const float* __restrict__ Wq_v, const float* __restrict__ Wk_v,
                       const float* __restrict__ Wv_v) {
    int idx = blockIdx.x * blockDim.x + threadIdx.x;
    if (idx >= 64 * 800) return;
    int d = idx / 800, c = idx % 800;
    float v;
    if (c < 256)      v = Wq_s[d * 256 + c];
    else if (c < 512) v = Wk_s[d * 256 + (c - 256)];
    else if (c < 608) v = Wq_v[d * 96 + (c - 512)];
    else if (c < 704) v = Wk_v[d * 96 + (c - 608)];
    else              v = Wv_v[d * 96 + (c - 704)];
    g_Bproj[idx] = v;
}

// g_wcat rows: [0:64) Wv_s@Wout[0:256]+Wv_v@Wout[256:352]; [64:96)<-Wout[352:384); [96:160)<-Wout[384:448)
__global__ void k_wfuse(const float* __restrict__ Wv_s, const float* __restrict__ Wv_v,
                        const float* __restrict__ Wout) {
    int idx = blockIdx.x * blockDim.x + threadIdx.x;
    if (idx >= 160 * 64) return;
    int r = idx >> 6, c = idx & 63;
    if (r < 64) {
        float acc = 0.f;
        for (int k = 0; k < 256; k++) acc += Wv_s[r * 256 + k] * Wout[k * 64 + c];
        for (int k = 0; k < 96; k++)  acc += Wv_v[r * 96 + k] * Wout[(256 + k) * 64 + c];
        g_wcat[idx] = acc;
    } else if (r < 96) {
        g_wcat[idx] = Wout[(352 + (r - 64)) * 64 + c];
    } else {
        g_wcat[idx] = Wout[(384 + (r - 96)) * 64 + c];
    }
}

// generic tiled SGEMM: 64x64 tile, 256 threads, 4x4 micro-tile
__device__ __forceinline__ void sgemm_body(const float* __restrict__ A, const float* __restrict__ B,
                                           const float* __restrict__ bias, float* __restrict__ C,
                                           int M, int N, int K) {
    __shared__ __align__(16) float As[64][17];
    __shared__ __align__(16) float Bs[16][64];
    int tid = threadIdx.x;
    int tx = tid & 15, ty = tid >> 4;
    int row0 = blockIdx.y * 64, col0 = blockIdx.x * 64;
    float acc[4][4] = {};
    int am = tid >> 2;
    int ak = (tid & 3) * 4;
    int bk = tid >> 6;
    int bn = tid & 63;

    for (int k0 = 0; k0 < K; k0 += 16) {
        int gr = row0 + am;
        float4 av = make_float4(0.f, 0.f, 0.f, 0.f);
        if (gr < M) av = *(const float4*)(A + (size_t)gr * K + k0 + ak);
        As[am][ak + 0] = av.x; As[am][ak + 1] = av.y; As[am][ak + 2] = av.z; As[am][ak + 3] = av.w;
        #pragma unroll
        for (int l = 0; l < 4; l++) {
            int kk = bk + l * 4;
            int gc = col0 + bn;
            Bs[kk][bn] = (gc < N) ? B[(size_t)(k0 + kk) * N + gc] : 0.f;
        }
        __syncthreads();
        #pragma unroll
        for (int kk = 0; kk < 16; kk++) {
            float a0 = As[ty * 4 + 0][kk], a1 = As[ty * 4 + 1][kk];
            float a2 = As[ty * 4 + 2][kk], a3 = As[ty * 4 + 3][kk];
            float4 bv = *(const float4*)&Bs[kk][tx * 4];
            acc[0][0] += a0 * bv.x; acc[0][1] += a0 * bv.y; acc[0][2] += a0 * bv.z; acc[0][3] += a0 * bv.w;
            acc[1][0] += a1 * bv.x; acc[1][1] += a1 * bv.y; acc[1][2] += a1 * bv.z; acc[1][3] += a1 * bv.w;
            acc[2][0] += a2 * bv.x; acc[2][1] += a2 * bv.y; acc[2][2] += a2 * bv.z; acc[2][3] += a2 * bv.w;
            acc[3][0] += a3 * bv.x; acc[3][1] += a3 * bv.y; acc[3][2] += a3 * bv.z; acc[3][3] += a3 * bv.w;
        }
        __syncthreads();
    }
    #pragma unroll
    for (int i = 0; i < 4; i++) {
        int gr = row0 + ty * 4 + i;
        if (gr >= M) continue;
        #pragma unroll
        for (int j = 0; j < 4; j++) {
            int gc = col0 + tx * 4 + j;
            if (gc < N) C[(size_t)gr * N + gc] = acc[i][j] + (bias ? bias[gc] : 0.f);
        }
    }
}

__global__ void k_gemm_proj(const float* __restrict__ s, int M) {
    sgemm_body(s, g_Bproj, nullptr, g_proj, M, 800, 64);
}
__global__ void k_gemm_out(const float* __restrict__ bout, float* __restrict__ out, int M) {
    sgemm_body(g_fin, g_wcat, bout, out, M, 64, 160);
}

__global__ void k_rotate(const float* __restrict__ quat, const float* __restrict__ trans, int N) {
    int idx = blockIdx.x * blockDim.x + threadIdx.x;
    if (idx >= N * 64) return;
    int n = idx >> 6, t = idx & 63;
    int isQ = (t < 32);
    int c = t & 31;
    const float* src = g_proj + (size_t)n * 800 + (isQ ? 512 : 608);
    float vx = src[c], vy = src[32 + c], vz = src[64 + c];
    float qw = quat[n * 4 + 0], qx = quat[n * 4 + 1], qy = quat[n * 4 + 2], qz = quat[n * 4 + 3];
    float uvx = qy * vz - qz * vy;
    float uvy = qz * vx - qx * vz;
    float uvz = qx * vy - qy * vx;
    float rx = vx + 2.f * (qw * uvx + (qy * uvz - qz * uvy));
    float ry = vy + 2.f * (qw * uvy + (qz * uvx - qx * uvz));
    float rz = vz + 2.f * (qw * uvz + (qx * uvy - qy * uvx));
    float* dst = (isQ ? g_qv : g_kv) + (size_t)n * 96 + c * 3;
    dst[0] = rx + trans[n * 3 + 0];
    dst[1] = ry + trans[n * 3 + 1];
    dst[2] = rz + trans[n * 3 + 2];
}

// warp per edge: attention logits (4 heads) + pair_z (16)
__global__ void k_edge(const int* __restrict__ ei, const int* __restrict__ ej,
                       const float* __restrict__ z,
                       const float* __restrict__ Wb, const float* __restrict__ bb,
                       const float* __restrict__ Wdz, const float* __restrict__ bdz,
                       const float* __restrict__ hw, int E) {
    __shared__ float sWb[256], sWdz[1024], sbb[4], shw[4], sbdz[16];
    __shared__ __align__(16) float sz[8][64];
    int tid = threadIdx.x;
    if (tid < 256) sWb[tid] = Wb[tid];
    for (int i = tid; i < 1024; i += 256) sWdz[i] = Wdz[i];
    if (tid < 4) { sbb[tid] = bb[tid]; shw[tid] = log1pf(__expf(hw[tid])); }
    if (tid < 16) sbdz[tid] = bdz[tid];
    __syncthreads();

    int lane = tid & 31, w = tid >> 5;
    int g = lane >> 3, r = lane & 7;
    int c16 = lane & 15, half = lane >> 4;

    int e = blockIdx.x * 8 + w;
    if (e >= E) return;
    int i = ei[e], j = ej[e];

    if (lane < 16) ((float4*)sz[w])[lane] = ((const float4*)(z + (size_t)e * 64))[lane];
    __syncwarp();

    // scalar dot: k_scalar[i,g] . q_scalar[j,g] (8 lanes per head, 8 elems each)
    const float* ksp = g_proj + (size_t)i * 800 + 256 + g * 64 + r * 8;
    const float* qsp = g_proj + (size_t)j * 800 + g * 64 + r * 8;
    float4 a0 = *(const float4*)ksp, a1 = *(const float4*)(ksp + 4);
    float4 b0 = *(const float4*)qsp, b1 = *(const float4*)(qsp + 4);
    float dot = a0.x * b0.x + a0.y * b0.y + a0.z * b0.z + a0.w * b0.w
              + a1.x * b1.x + a1.y * b1.y + a1.z * b1.z + a1.w * b1.w;

    // vec: |qv[i,p] - kv[j,p]|^2, point p = r of head g
    const float* qvp = g_qv + (size_t)i * 96 + (g * 8 + r) * 3;
    const float* kvp = g_kv + (size_t)j * 96 + (g * 8 + r) * 3;
    float dx = qvp[0] - kvp[0], dy = qvp[1] - kvp[1], dz = qvp[2] - kvp[2];
    float vsq = dx * dx + dy * dy + dz * dz;

    // bias partial: z[e,d] @ Wb[d,g], d = r*8..r*8+8
    float bias = 0.f;
    const float* zr = sz[w] + r * 8;
    #pragma unroll
    for (int d = 0; d < 8; d++) bias += zr[d] * sWb[(r * 8 + d) * 4 + g];

    float part = dot * SC_DOT + bias * SC_B + vsq * SC_V * shw[g];
    part += __shfl_xor_sync(~0u, part, 1, 8);
    part += __shfl_xor_sync(~0u, part, 2, 8);
    part += __shfl_xor_sync(~0u, part, 4, 8);
    if (r == 0) g_logit[(size_t)e * 4 + g] = part + SC_B * sbb[g];

    // pair_z[e,c16] = z[e] @ Wdz[:,c16] + bdz (2 lanes per output)
    float pc = 0.f;
    const float* zh = sz[w] + half * 32;
    const float* wd = sWdz + (size_t)half * 32 * 16 + c16;
    #pragma unroll
    for (int d = 0; d < 32; d++) pc += zh[d] * wd[d * 16];
    pc += __shfl_xor_sync(~0u, pc, 16);
    if (lane < 16) g_pairz[(size_t)e * 16 + c16] = pc + sbdz[c16];
}

// warp per node: segment softmax + pair aggregation + feature assembly
__global__ void k_node(const float* __restrict__ s, int N) {
    int lane = threadIdx.x & 31, w = threadIdx.x >> 5;
    int n = blockIdx.x * 8 + w;
    if (n >= N) return;
    int off = g_off[n], deg = g_cnt[n];
    int h = lane >> 3, r = lane & 7;

    // per-head max
    float mx = -CUDART_INF_F;
    for (int t = r; t < deg; t += 8) {
        int e = g_el[off + t];
        mx = fmaxf(mx, g_logit[(size_t)e * 4 + h]);
    }
    mx = fmaxf(mx, __shfl_xor_sync(~0u, mx, 1, 8));
    mx = fmaxf(mx, __shfl_xor_sync(~0u, mx, 2, 8));
    mx = fmaxf(mx, __shfl_xor_sync(~0u, mx, 4, 8));

    // per-head sum of exp
    float sm = 0.f;
    for (int t = r; t < deg; t += 8) {
        int e = g_el[off + t];
        sm += __expf(g_logit[(size_t)e * 4 + h] - mx);
    }
    sm += __shfl_xor_sync(~0u, sm, 1, 8);
    sm += __shfl_xor_sync(~0u, sm, 2, 8);
    sm += __shfl_xor_sync(~0u, sm, 4, 8);
    float inv = (sm > 0.f) ? (1.f / sm) : 0.f;

    // aggregation layout: lane owns c = lane&15 for heads hh and hh+2
    int c = lane & 15, hh = lane >> 4;
    float m0 = __shfl_sync(~0u, mx, hh * 8);
    float m1 = __shfl_sync(~0u, mx, (hh + 2) * 8);
    float i0 = __shfl_sync(~0u, inv, hh * 8);
    float i1 = __shfl_sync(~0u, inv, (hh + 2) * 8);
    float acc0 = 0.f, acc1 = 0.f;
    for (int t = 0; t < deg; t++) {
        int e = g_el[off + t];
        float pz = g_pairz[(size_t)e * 16 + c];
        float w0 = __expf(g_logit[(size_t)e * 4 + hh] - m0);
        float w1 = __expf(g_logit[(size_t)e * 4 + hh + 2] - m1);
        acc0 += w0 * pz; acc1 += w1 * pz;
    }
    float* fin = g_fin + (size_t)n * 160;
    fin[96 + hh * 16 + c] = acc0 * i0;
    fin[96 + (hh + 2) * 16 + c] = acc1 * i1;

    // copy s (64 floats) and compute 32 point norms from vv projection
    float2 sv = ((const float2*)(s + (size_t)n * 64))[lane];
    ((float2*)fin)[lane] = sv;
    const float* vv = g_proj + (size_t)n * 800 + 704;
    float px = vv[lane], py = vv[32 + lane], pz2 = vv[64 + lane];
    fin[64 + lane] = sqrtf(px * px + py * py + pz2 * pz2 + 1e-8f);
}

extern "C" void kernel_launch(void* const* d_in, const int* in_sizes, int n_in,
                              void* d_out, int out_size) {
    const float* s     = (const float*)d_in[0];
    const float* z     = (const float*)d_in[1];
    const int*   eidx  = (const int*)d_in[2];
    const float* quat  = (const float*)d_in[3];
    const float* trans = (const float*)d_in[4];
    const float* Wq_s  = (const float*)d_in[5];
    const float* Wk_s  = (const float*)d_in[6];
    const float* Wv_s  = (const float*)d_in[7];
    const float* Wq_v  = (const float*)d_in[8];
    const float* Wk_v  = (const float*)d_in[9];
    const float* Wv_v  = (const float*)d_in[10];
    const float* Wb    = (const float*)d_in[11];
    const float* bb    = (const float*)d_in[12];
    const float* Wdz   = (const float*)d_in[13];
    const float* bdz   = (const float*)d_in[14];
    const float* hw    = (const float*)d_in[15];
    const float* Wout  = (const float*)d_in[16];
    const float* bout  = (const float*)d_in[17];
    float* out = (float*)d_out;

    int N = in_sizes[0] / 64;
    int E = in_sizes[2] / 2;
    const int* ei = eidx;
    const int* ej = eidx + E;

    k_init<<<(N + 255) / 256, 256>>>(N);
    k_count<<<(E + 255) / 256, 256>>>(ei, E);
    k_scan<<<1, 1024>>>(N);
    k_scatter<<<(E + 255) / 256, 256>>>(ei, E);
    k_pack<<<(64 * 800 + 255) / 256, 256>>>(Wq_s, Wk_s, Wq_v, Wk_v, Wv_v);
    k_wfuse<<<(160 * 64 + 255) / 256, 256>>>(Wv_s, Wv_v, Wout);

    dim3 gproj(13, (N + 63) / 64);
    k_gemm_proj<<<gproj, 256>>>(s, N);

    k_rotate<<<(N * 64 + 255) / 256, 256>>>(quat, trans, N);
    k_edge<<<(E + 7) / 8, 256>>>(ei, ej, z, Wb, bb, Wdz, bdz, hw, E);
    k_node<<<(N + 7) / 8, 256>>>(s, N);

    dim3 gout(1, (N + 63) / 64);
    k_gemm_out<<<gout, 256>>>(bout, out, N);
}